// round 1
// baseline (speedup 1.0000x reference)
#include <cuda_runtime.h>
#include <math.h>

#define S_LEN 1024
#define BATCH 128
#define DIN 256
#define NQ 8
#define FAN 264      // DIN + NQ
#define NOUT 32      // 4 gates * 8 qubits

// 16 MB scratch for precomputed x-part of gate pre-activations
__device__ float g_Px[S_LEN * BATCH * NOUT];

#define FULLMASK 0xffffffffu
__device__ __forceinline__ float shfl(float v, int src) { return __shfl_sync(FULLMASK, v, src); }
__device__ __forceinline__ float shflx(float v, int m)  { return __shfl_xor_sync(FULLMASK, v, m); }

// ---------------------------------------------------------------------------
// Kernel 1: Px[s,b,g*8+q] = x[s,b,:] . W_g[q,:256] + b_g[q]
// block = 256 threads: 16 k-slices (part) x 16 output-pairs (og)
// W slice held in registers; x row staged in smem; shfl-tree reduce.
// ---------------------------------------------------------------------------
__global__ void __launch_bounds__(256) px_kernel(
    const float* __restrict__ x,
    const float* __restrict__ W0, const float* __restrict__ B0,
    const float* __restrict__ W1, const float* __restrict__ B1,
    const float* __restrict__ W2, const float* __restrict__ B2,
    const float* __restrict__ W3, const float* __restrict__ B3)
{
    __shared__ float xsh[DIN];
    const int t    = threadIdx.x;
    const int part = t & 15;     // k = j*16 + part
    const int og   = t >> 4;     // 0..15 -> outputs 2*og, 2*og+1
    const int o0 = og * 2, o1 = o0 + 1;

    const float* Wp[4] = {W0, W1, W2, W3};
    const float* Bp[4] = {B0, B1, B2, B3};
    const float* w0p = Wp[o0 >> 3] + (o0 & 7) * FAN;
    const float* w1p = Wp[o1 >> 3] + (o1 & 7) * FAN;

    float w0[16], w1[16];
#pragma unroll
    for (int j = 0; j < 16; j++) {
        w0[j] = w0p[j * 16 + part];
        w1[j] = w1p[j * 16 + part];
    }
    const float bias0 = Bp[o0 >> 3][o0 & 7];
    const float bias1 = Bp[o1 >> 3][o1 & 7];

    const int ROWS = S_LEN * BATCH;
    const int rpb  = ROWS / gridDim.x;
    const long base = (long)blockIdx.x * rpb;

    for (int r = 0; r < rpb; r++) {
        const long row = base + r;
        __syncthreads();
        xsh[t] = x[row * DIN + t];
        __syncthreads();

        float a0 = 0.f, a1 = 0.f;
#pragma unroll
        for (int j = 0; j < 16; j++) {
            float xv = xsh[j * 16 + part];
            a0 = fmaf(xv, w0[j], a0);
            a1 = fmaf(xv, w1[j], a1);
        }
#pragma unroll
        for (int m = 1; m < 16; m <<= 1) {
            a0 += shflx(a0, m);
            a1 += shflx(a1, m);
        }
        if (part == 0) {
            g_Px[row * NOUT + o0] = a0 + bias0;
            g_Px[row * NOUT + o1] = a1 + bias1;
        }
    }
}

// ---------------------------------------------------------------------------
// Kernel 2: sequential recurrence. block = batch element (4 warps = 4 gates),
// one warp = one 8-qubit statevector sim (8 complex amps per lane).
// Lane bits: wire0=16, wire1=8, wire2=4, wire3=2, wire4=1.
// Reg bits : wire5=4, wire6=2, wire7=1.
// Sparsity of |0..0> start: wires 0..4 act on reg0 only; regs fill at w=5..7.
// ---------------------------------------------------------------------------
__global__ void __launch_bounds__(128) qlstm_kernel(
    const float* __restrict__ Wf, const float* __restrict__ Wi,
    const float* __restrict__ Wu, const float* __restrict__ Wo,
    float* __restrict__ out)
{
    const int b    = blockIdx.x;      // batch element
    const int tid  = threadIdx.x;
    const int warp = tid >> 5;        // gate: 0=f 1=i 2=u 3=o
    const int lane = tid & 31;

    __shared__ float P[2][4][NQ];     // double-buffered normalized probs

    // Wh: lane q<8 holds Wh[q][0..7]
    const float* Wg = (warp == 0) ? Wf : (warp == 1) ? Wi : (warp == 2) ? Wu : Wo;
    float wh[NQ];
#pragma unroll
    for (int j = 0; j < NQ; j++)
        wh[j] = (lane < NQ) ? Wg[lane * FAN + DIN + j] : 0.f;

    float h = 0.f, c = 0.f;
    float px = (lane < NQ) ? g_Px[((long)0 * BATCH + b) * NOUT + warp * NQ + lane] : 0.f;

    for (int s = 0; s < S_LEN; s++) {
        // prefetch next step's Px (independent of h)
        float pxn = 0.f;
        if (lane < NQ) {
            int snx = (s + 1 < S_LEN) ? s + 1 : s;
            pxn = g_Px[((long)snx * BATCH + b) * NOUT + warp * NQ + lane];
        }

        // params: p[q] = Px + sum_j Wh[q][j] * h[j]
        float p = px;
#pragma unroll
        for (int j = 0; j < NQ; j++)
            p = fmaf(wh[j], shfl(h, j), p);
        if (lane >= NQ) p = 0.f;

        float sn2, cs;
        sincosf(0.5f * p, &sn2, &cs);   // lane q holds sin/cos of param[q]/2

        // ---------------- circuit sim ----------------
        float a0r = (lane == 0) ? 1.f : 0.f, a0i = 0.f;
        float a1r, a1i, a2r, a2i, a3r, a3i, a4r, a4i, a5r, a5i, a6r, a6i, a7r, a7i;

        // wires 0..3 : cross-lane, reg0 only
#pragma unroll
        for (int w = 0; w < 4; w++) {
            const int Lm = 16 >> w;
            float cw = shfl(cs, w), sw = shfl(sn2, w);
            float pr = shflx(a0r, Lm), pi = shflx(a0i, Lm);
            float nr = cw * a0r + sw * pi;          // RX: new = c*own + (-i s)*other
            float ni = cw * a0i - sw * pr;
            float zc = shfl(cs, w + 1), zs = shfl(sn2, w + 1);
            float sg = (lane & Lm) ? zs : -zs;      // RZ: bit1 -> conj phase
            a0r = zc * nr - sg * ni;
            a0i = zc * ni + sg * nr;
            const int Tm = Lm >> 1;                 // CNOT(w, w+1): both cross-lane
            pr = shflx(a0r, Tm); pi = shflx(a0i, Tm);
            if (lane & Lm) { a0r = pr; a0i = pi; }
        }

        // wire 4 : cross-lane (mask 1), reg0 only; CNOT(4,5) goes into regs
        {
            float cw = shfl(cs, 4), sw = shfl(sn2, 4);
            float pr = shflx(a0r, 1), pi = shflx(a0i, 1);
            float nr = cw * a0r + sw * pi;
            float ni = cw * a0i - sw * pr;
            float zc = shfl(cs, 5), zs = shfl(sn2, 5);
            float sg = (lane & 1) ? zs : -zs;
            a0r = zc * nr - sg * ni;
            a0i = zc * ni + sg * nr;
        }
        {   // CNOT(4,5): odd lanes move reg0 -> reg4
            bool odd = (lane & 1);
            a4r = odd ? a0r : 0.f;  a4i = odd ? a0i : 0.f;
            a0r = odd ? 0.f : a0r;  a0i = odd ? 0.f : a0i;
        }

        // wire 5 (reg bit 4): active {0,4}
        {
            float cw = shfl(cs, 5), sw = shfl(sn2, 5);
            float n0r = cw * a0r + sw * a4i;
            float n0i = cw * a0i - sw * a4r;
            float n4r = cw * a4r + sw * a0i;
            float n4i = cw * a4i - sw * a0r;
            float zc = shfl(cs, 6), zs = shfl(sn2, 6);
            a0r = zc * n0r + zs * n0i;  a0i = zc * n0i - zs * n0r;  // bit=0
            a4r = zc * n4r - zs * n4i;  a4i = zc * n4i + zs * n4r;  // bit=1
        }
        // CNOT(5,6): 4 -> 6 (5,7 are zero)
        a6r = a4r; a6i = a4i;

        // wire 6 (reg bit 2): active {0,6}; pairs (0,2) and (4,6) with one side zero
        {
            float cw = shfl(cs, 6), sw = shfl(sn2, 6);
            float n0r = cw * a0r,  n0i = cw * a0i;
            float n2r = sw * a0i,  n2i = -sw * a0r;
            float n6r = cw * a6r,  n6i = cw * a6i;
            float n4r = sw * a6i,  n4i = -sw * a6r;
            float zc = shfl(cs, 7), zs = shfl(sn2, 7);
            a0r = zc * n0r + zs * n0i;  a0i = zc * n0i - zs * n0r;  // bit2=0
            a4r = zc * n4r + zs * n4i;  a4i = zc * n4i - zs * n4r;  // bit2=0
            a2r = zc * n2r - zs * n2i;  a2i = zc * n2i + zs * n2r;  // bit2=1
            a6r = zc * n6r - zs * n6i;  a6i = zc * n6i + zs * n6r;  // bit2=1
        }
        // CNOT(6,7): 2->3, 6->7
        a3r = a2r; a3i = a2i;  a7r = a6r; a7i = a6i;

        // wire 7 (reg bit 1): active {0,3,4,7}; pairs (0,1),(2,3),(4,5),(6,7)
        {
            float cw = shfl(cs, 7), sw = shfl(sn2, 7);
            float n0r = cw * a0r,  n0i = cw * a0i;
            float n1r = sw * a0i,  n1i = -sw * a0r;
            float n3r = cw * a3r,  n3i = cw * a3i;
            float n2r = sw * a3i,  n2i = -sw * a3r;
            float n4r = cw * a4r,  n4i = cw * a4i;
            float n5r = sw * a4i,  n5i = -sw * a4r;
            float n7r = cw * a7r,  n7i = cw * a7i;
            float n6r = sw * a7i,  n6i = -sw * a7r;
            float zc = shfl(cs, 0), zs = shfl(sn2, 0);
            a0r = zc * n0r + zs * n0i;  a0i = zc * n0i - zs * n0r;
            a2r = zc * n2r + zs * n2i;  a2i = zc * n2i - zs * n2r;
            a4r = zc * n4r + zs * n4i;  a4i = zc * n4i - zs * n4r;
            a6r = zc * n6r + zs * n6i;  a6i = zc * n6i - zs * n6r;
            a1r = zc * n1r - zs * n1i;  a1i = zc * n1i + zs * n1r;
            a3r = zc * n3r - zs * n3i;  a3i = zc * n3i + zs * n3r;
            a5r = zc * n5r - zs * n5i;  a5i = zc * n5i + zs * n5r;
            a7r = zc * n7r - zs * n7i;  a7i = zc * n7i + zs * n7r;
            // CNOT(7,0): odd regs swap across lane^16
            a1r = shflx(a1r, 16); a1i = shflx(a1i, 16);
            a3r = shflx(a3r, 16); a3i = shflx(a3i, 16);
            a5r = shflx(a5r, 16); a5i = shflx(a5i, 16);
            a7r = shflx(a7r, 16); a7i = shflx(a7i, 16);
        }

        // probs: first 8 basis states live entirely on lane 0 (regs 0..7)
        if (lane == 0) {
            float q0 = a0r * a0r + a0i * a0i;
            float q1 = a1r * a1r + a1i * a1i;
            float q2 = a2r * a2r + a2i * a2i;
            float q3 = a3r * a3r + a3i * a3i;
            float q4 = a4r * a4r + a4i * a4i;
            float q5 = a5r * a5r + a5i * a5i;
            float q6 = a6r * a6r + a6i * a6i;
            float q7 = a7r * a7r + a7i * a7i;
            float ssum = ((q0 + q1) + (q2 + q3)) + ((q4 + q5) + (q6 + q7));
            float inv = 1.0f / ssum;
            float* Pw = &P[s & 1][warp][0];
            Pw[0] = q0 * inv; Pw[1] = q1 * inv; Pw[2] = q2 * inv; Pw[3] = q3 * inv;
            Pw[4] = q4 * inv; Pw[5] = q5 * inv; Pw[6] = q6 * inv; Pw[7] = q7 * inv;
        }
        __syncthreads();

        // combine (replicated in every warp -> single barrier per step)
        if (lane < NQ) {
            const int bs = s & 1;
            float f_ = P[bs][0][lane];
            float i_ = P[bs][1][lane];
            float u_ = P[bs][2][lane];
            float o_ = P[bs][3][lane];
            float g_ = tanhf(u_);
            c = f_ * c + i_ * g_;
            h = o_ * tanhf(c);
            if (warp == 0)
                out[(long)s * (BATCH * NQ) + b * NQ + lane] = h;
        }
        px = pxn;
    }

    if (warp == 0 && lane < NQ) {
        const long ob = (long)S_LEN * BATCH * NQ;
        out[ob + b * NQ + lane] = h;                  // h_n
        out[ob + BATCH * NQ + b * NQ + lane] = c;     // c_n
    }
}

// ---------------------------------------------------------------------------
extern "C" void kernel_launch(void* const* d_in, const int* in_sizes, int n_in,
                              void* d_out, int out_size)
{
    const float* x  = (const float*)d_in[0];
    const float* Wf = (const float*)d_in[1];
    const float* bf = (const float*)d_in[2];
    const float* Wi = (const float*)d_in[3];
    const float* bi = (const float*)d_in[4];
    const float* Wu = (const float*)d_in[5];
    const float* bu = (const float*)d_in[6];
    const float* Wo = (const float*)d_in[7];
    const float* bo = (const float*)d_in[8];
    float* out = (float*)d_out;

    px_kernel<<<4096, 256>>>(x, Wf, bf, Wi, bi, Wu, bu, Wo, bo);
    qlstm_kernel<<<BATCH, 128>>>(Wf, Wi, Wu, Wo, out);
}

// round 3
// speedup vs baseline: 1.5341x; 1.5341x over previous
#include <cuda_runtime.h>
#include <math.h>

#define S_LEN 1024
#define BATCH 128
#define DIN 256
#define NQ 8
#define FAN 264      // DIN + NQ
#define NPX 20       // 4 gates * 5 needed params (q in {0,1,5,6,7})

// scratch for precomputed x-part of the 20 needed gate pre-activations
__device__ float g_Px[S_LEN * BATCH * NPX];

#define FULLMASK 0xffffffffu
__device__ __forceinline__ float shfl(float v, int src) { return __shfl_sync(FULLMASK, v, src); }
__device__ __forceinline__ float shflx(float v, int m)  { return __shfl_xor_sync(FULLMASK, v, m); }

// Overflow-safe fast tanh: 1 - 2/(exp(2v)+1).
// exp overflow -> inf -> 2/inf = 0 -> returns 1 (no inf/inf NaN).
__device__ __forceinline__ float ftanh(float v) {
    float e = __expf(2.0f * v);
    return 1.0f - __fdividef(2.0f, e + 1.0f);
}

// ---------------------------------------------------------------------------
// Kernel 1: Px[row, g*5+qi] = x[row,:] . W_g[q,:256] + b_g[q], q in {0,1,5,6,7}
// block = 160 threads = 20 outputs x 8 k-parts; 4 rows per iteration.
// ---------------------------------------------------------------------------
__global__ void __launch_bounds__(160) px_kernel(
    const float* __restrict__ x,
    const float* __restrict__ W0, const float* __restrict__ B0,
    const float* __restrict__ W1, const float* __restrict__ B1,
    const float* __restrict__ W2, const float* __restrict__ B2,
    const float* __restrict__ W3, const float* __restrict__ B3)
{
    __shared__ float xsh[4 * 256];
    const int t    = threadIdx.x;
    const int og   = t >> 3;       // 0..19
    const int part = t & 7;        // k = jj*8 + part
    const int g    = og / 5;
    const int qi   = og % 5;
    const int q    = (qi == 0) ? 0 : (qi == 1) ? 1 : (qi == 2) ? 5 : (qi == 3) ? 6 : 7;

    const float* Wp[4] = {W0, W1, W2, W3};
    const float* Bp[4] = {B0, B1, B2, B3};
    const float* Wr = Wp[g] + q * FAN;

    float w[32];
#pragma unroll
    for (int jj = 0; jj < 32; jj++) w[jj] = Wr[jj * 8 + part];
    const float bias = Bp[g][q];

    const int rpb   = (S_LEN * BATCH) / gridDim.x;
    const long base = (long)blockIdx.x * rpb;

    for (int r0 = 0; r0 < rpb; r0 += 4) {
        __syncthreads();
        const float4* src = (const float4*)(x + (base + r0) * DIN);
        for (int i = t; i < 256; i += 160) ((float4*)xsh)[i] = src[i];
        __syncthreads();

        float a0 = 0.f, a1 = 0.f, a2 = 0.f, a3 = 0.f;
#pragma unroll
        for (int jj = 0; jj < 32; jj++) {
            const int k = jj * 8 + part;
            a0 = fmaf(w[jj], xsh[k],       a0);
            a1 = fmaf(w[jj], xsh[256 + k], a1);
            a2 = fmaf(w[jj], xsh[512 + k], a2);
            a3 = fmaf(w[jj], xsh[768 + k], a3);
        }
#pragma unroll
        for (int m = 1; m < 8; m <<= 1) {
            a0 += shflx(a0, m); a1 += shflx(a1, m);
            a2 += shflx(a2, m); a3 += shflx(a3, m);
        }
        if (part == 0) {
            float* dst = &g_Px[(base + r0) * NPX + og];
            dst[0]       = a0 + bias;
            dst[NPX]     = a1 + bias;
            dst[2 * NPX] = a2 + bias;
            dst[3 * NPX] = a3 + bias;
        }
    }
}

// ---------------------------------------------------------------------------
// Kernel 2: sequential recurrence, closed-form circuit probabilities.
// One warp per batch element. lane = gate*8 + j.
// Derivation (no interference in the RX/RZ/CNOT ring from |0..0>):
//   x_w = cos^2(theta_w / 2)
//   P_j ∝ A(v7) * X5(v5) * X6(v5^v6) * X7(v6^v7),  j = 4*v5 + 2*v6 + v7
//   A(0) = x0*x1, A(1) = (1-x0)(1-x1); Xw(0)=x_w, Xw(1)=1-x_w
//   Sum_j P_j = (A0+A1)/2 + (A0-A1)/2 * (2x5-1)(2x6-1)(2x7-1)   (exact)
// ---------------------------------------------------------------------------
__global__ void __launch_bounds__(32) qlstm_kernel(
    const float* __restrict__ Wf, const float* __restrict__ Wi,
    const float* __restrict__ Wu, const float* __restrict__ Wo,
    float* __restrict__ out)
{
    const int b     = blockIdx.x;
    const int lane  = threadIdx.x;
    const int g     = lane >> 3;
    const int j     = lane & 7;
    const int gbase = lane & 24;

    const int  w5 = (j >> 2) & 1, w6 = (j >> 1) & 1, w7 = j & 1;
    const bool selA1 = (w7 != 0);
    const bool fl5   = (w5 != 0);
    const bool fl6   = ((w5 ^ w6) != 0);
    const bool fl7   = ((w6 ^ w7) != 0);

    const float* Wg = (g == 0) ? Wf : (g == 1) ? Wi : (g == 2) ? Wu : Wo;
    const int q = (j == 0) ? 0 : (j == 1) ? 1 : (j == 2) ? 5 : (j == 3) ? 6 : 7;
    const bool par = (j < 5);

    float wh[8];
#pragma unroll
    for (int jj = 0; jj < 8; jj++)
        wh[jj] = par ? Wg[q * FAN + DIN + jj] : 0.f;

    float h = 0.f, c = 0.f;
    float px = par ? g_Px[(long)b * NPX + g * 5 + j] : 0.f;

    for (int s = 0; s < S_LEN; s++) {
        // prefetch next step's Px (off the critical path)
        float pxn = 0.f;
        if (par) {
            const int sn = (s + 1 < S_LEN) ? s + 1 : s;
            pxn = g_Px[((long)sn * BATCH + b) * NPX + g * 5 + j];
        }

        // parameter: p = px + Wh . h  (split into two chains)
        float pa = px, pb = 0.f;
        pa = fmaf(wh[0], shfl(h, 0), pa);
        pa = fmaf(wh[1], shfl(h, 1), pa);
        pa = fmaf(wh[2], shfl(h, 2), pa);
        pa = fmaf(wh[3], shfl(h, 3), pa);
        pb = fmaf(wh[4], shfl(h, 4), pb);
        pb = fmaf(wh[5], shfl(h, 5), pb);
        pb = fmaf(wh[6], shfl(h, 6), pb);
        pb = fmaf(wh[7], shfl(h, 7), pb);
        const float p = pa + pb;

        const float xq = fmaf(0.5f, __cosf(p), 0.5f);   // cos^2(p/2)

        // broadcast this gate's 5 relevant x values within the 8-lane group
        const float x0 = shfl(xq, gbase + 0);
        const float x1 = shfl(xq, gbase + 1);
        const float x5 = shfl(xq, gbase + 2);
        const float x6 = shfl(xq, gbase + 3);
        const float x7 = shfl(xq, gbase + 4);

        const float A0 = x0 * x1;
        const float A1 = (1.f - x0) * (1.f - x1);
        const float A  = selA1 ? A1 : A0;
        const float F5 = fl5 ? (1.f - x5) : x5;
        const float F6 = fl6 ? (1.f - x6) : x6;
        const float F7 = fl7 ? (1.f - x7) : x7;
        const float P  = (A * F5) * (F6 * F7);

        const float d5 = fmaf(2.f, x5, -1.f);
        const float d6 = fmaf(2.f, x6, -1.f);
        const float d7 = fmaf(2.f, x7, -1.f);
        float Ssum = fmaf(0.5f * (A0 - A1), (d5 * d6) * d7, 0.5f * (A0 + A1));
        Ssum = fmaxf(Ssum, 1e-30f);      // guard measure-zero A0=A1=0 case

        const float prob = P * __frcp_rn(Ssum) ;

        // gather the 4 gate probabilities for this lane's qubit j
        const float pf = shfl(prob, j);
        const float pi = shfl(prob, 8 + j);
        const float pu = shfl(prob, 16 + j);
        const float po = shfl(prob, 24 + j);

        const float gg = ftanh(pu);
        c = fmaf(pf, c, pi * gg);
        h = po * ftanh(c);

        if (lane < NQ)
            out[(long)s * (BATCH * NQ) + b * NQ + lane] = h;
        px = pxn;
    }

    if (lane < NQ) {
        const long ob = (long)S_LEN * BATCH * NQ;
        out[ob + b * NQ + lane] = h;                    // h_n
        out[ob + BATCH * NQ + b * NQ + lane] = c;       // c_n
    }
}

// ---------------------------------------------------------------------------
extern "C" void kernel_launch(void* const* d_in, const int* in_sizes, int n_in,
                              void* d_out, int out_size)
{
    const float* x  = (const float*)d_in[0];
    const float* Wf = (const float*)d_in[1];
    const float* bf = (const float*)d_in[2];
    const float* Wi = (const float*)d_in[3];
    const float* bi = (const float*)d_in[4];
    const float* Wu = (const float*)d_in[5];
    const float* bu = (const float*)d_in[6];
    const float* Wo = (const float*)d_in[7];
    const float* bo = (const float*)d_in[8];
    float* out = (float*)d_out;

    px_kernel<<<2048, 160>>>(x, Wf, bf, Wi, bi, Wu, bu, Wo, bo);
    qlstm_kernel<<<BATCH, 32>>>(Wf, Wi, Wu, Wo, out);
}

// round 4
// speedup vs baseline: 1.8630x; 1.2143x over previous
#include <cuda_runtime.h>
#include <math.h>

#define S_LEN 1024
#define BATCH 128
#define DIN 256
#define NQ 8
#define FAN 264      // DIN + NQ
#define NPX 20       // 4 gates * 5 needed params (q in {0,1,5,6,7})

// precomputed x-part of gate pre-activations, B-MAJOR: [b][s][20]
__device__ float g_Px[BATCH * S_LEN * NPX];

#define FULLMASK 0xffffffffu
__device__ __forceinline__ float shfl(float v, int src) { return __shfl_sync(FULLMASK, v, src); }
__device__ __forceinline__ float shflx(float v, int m)  { return __shfl_xor_sync(FULLMASK, v, m); }

// Overflow-safe fast tanh: 1 - 2/(exp(2v)+1). inf-safe at both ends.
__device__ __forceinline__ float ftanh(float v) {
    float e = __expf(2.0f * v);
    return 1.0f - __fdividef(2.0f, e + 1.0f);
}

// ---------------------------------------------------------------------------
// Kernel 1: Px[b][s][g*5+qi] = x[s,b,:] . W_g[q,:256] + b_g[q], q in {0,1,5,6,7}
// block = 160 threads = 20 outputs x 8 k-parts; 4 rows (consecutive b) per iter.
// ---------------------------------------------------------------------------
__global__ void __launch_bounds__(160) px_kernel(
    const float* __restrict__ x,
    const float* __restrict__ W0, const float* __restrict__ B0,
    const float* __restrict__ W1, const float* __restrict__ B1,
    const float* __restrict__ W2, const float* __restrict__ B2,
    const float* __restrict__ W3, const float* __restrict__ B3)
{
    __shared__ float xsh[4 * 256];
    const int t    = threadIdx.x;
    const int og   = t >> 3;       // 0..19
    const int part = t & 7;        // k = jj*8 + part
    const int g    = og / 5;
    const int qi   = og % 5;
    const int q    = (qi == 0) ? 0 : (qi == 1) ? 1 : (qi == 2) ? 5 : (qi == 3) ? 6 : 7;

    const float* Wp[4] = {W0, W1, W2, W3};
    const float* Bp[4] = {B0, B1, B2, B3};
    const float* Wr = Wp[g] + q * FAN;

    float w[32];
#pragma unroll
    for (int jj = 0; jj < 32; jj++) w[jj] = Wr[jj * 8 + part];
    const float bias = Bp[g][q];

    const int rpb   = (S_LEN * BATCH) / gridDim.x;
    const long base = (long)blockIdx.x * rpb;

    for (int r0 = 0; r0 < rpb; r0 += 4) {
        __syncthreads();
        const float4* src = (const float4*)(x + (base + r0) * DIN);
        for (int i = t; i < 256; i += 160) ((float4*)xsh)[i] = src[i];
        __syncthreads();

        float a0 = 0.f, a1 = 0.f, a2 = 0.f, a3 = 0.f;
#pragma unroll
        for (int jj = 0; jj < 32; jj++) {
            const int k = jj * 8 + part;
            a0 = fmaf(w[jj], xsh[k],       a0);
            a1 = fmaf(w[jj], xsh[256 + k], a1);
            a2 = fmaf(w[jj], xsh[512 + k], a2);
            a3 = fmaf(w[jj], xsh[768 + k], a3);
        }
#pragma unroll
        for (int m = 1; m < 8; m <<= 1) {
            a0 += shflx(a0, m); a1 += shflx(a1, m);
            a2 += shflx(a2, m); a3 += shflx(a3, m);
        }
        if (part == 0) {
            // row r = s*BATCH + b  ->  write b-major [b][s][og]
            const long r = base + r0;
            const int  s = (int)(r >> 7);        // BATCH = 128
            const int  b = (int)(r & 127);       // rows r..r+3 -> b..b+3, same s
            float* dst = &g_Px[((long)b * S_LEN + s) * NPX + og];
            const long bstride = (long)S_LEN * NPX;
            dst[0]           = a0 + bias;
            dst[bstride]     = a1 + bias;
            dst[2 * bstride] = a2 + bias;
            dst[3 * bstride] = a3 + bias;
        }
    }
}

// ---------------------------------------------------------------------------
// Kernel 2: sequential recurrence, closed-form circuit probs in y = cos(p) form.
// One warp per batch element; lane = gate*8 + j. Each lane computes its gate's
// 5 params itself (no y-broadcast stage). j = 4*v5 + 2*v6 + v7:
//   num = (1 s0 y0)(1 s0 y1)(1+s5 y5)(1+s6 y6)(1+s7 y7),
//     s0 = v7?-1:+1, s5 = v5?-1:+1, s6 = (v5^v6)?-1:+1, s7 = (v6^v7)?-1:+1
//   den = 8*[(1 + y0*y1) + (y0+y1)*y5*y6*y7]
// ---------------------------------------------------------------------------
__global__ void __launch_bounds__(32) qlstm_kernel(
    const float* __restrict__ Wf, const float* __restrict__ Wi,
    const float* __restrict__ Wu, const float* __restrict__ Wo,
    float* __restrict__ out)
{
    const int b    = blockIdx.x;
    const int lane = threadIdx.x;
    const int g    = lane >> 3;
    const int j    = lane & 7;

    const int  v5 = (j >> 2) & 1, v6 = (j >> 1) & 1, v7 = j & 1;
    const float s0 = v7 ? -1.f : 1.f;
    const float s5 = v5 ? -1.f : 1.f;
    const float s6 = (v5 ^ v6) ? -1.f : 1.f;
    const float s7 = (v6 ^ v7) ? -1.f : 1.f;

    const float* Wg = (g == 0) ? Wf : (g == 1) ? Wi : (g == 2) ? Wu : Wo;
    const int qlist[5] = {0, 1, 5, 6, 7};

    // every lane holds its gate's full 5x8 recurrent weight block
    float wh[5][8];
#pragma unroll
    for (int i = 0; i < 5; i++)
#pragma unroll
        for (int jj = 0; jj < 8; jj++)
            wh[i][jj] = Wg[qlist[i] * FAN + DIN + jj];

    const float* pxbase = &g_Px[((long)b * S_LEN) * NPX + g * 5];

    float h = 0.f, c = 0.f;
    float px0[5], px1[5];
#pragma unroll
    for (int i = 0; i < 5; i++) {
        px0[i] = pxbase[i];            // s = 0
        px1[i] = pxbase[NPX + i];      // s = 1
    }

#pragma unroll 2
    for (int s = 0; s < S_LEN; s++) {
        // prefetch step s+2 (two full bodies of slack)
        float px2[5];
        {
            const int sp = (s + 2 < S_LEN) ? s + 2 : S_LEN - 1;
            const float* pp = pxbase + (long)sp * NPX;
#pragma unroll
            for (int i = 0; i < 5; i++) px2[i] = pp[i];
        }

        // broadcast h (one shfl stage)
        float hs[8];
#pragma unroll
        for (int jj = 0; jj < 8; jj++) hs[jj] = shfl(h, jj);

        // 5 params for this lane's gate; two FMA chains each
        float y[5];
#pragma unroll
        for (int i = 0; i < 5; i++) {
            float pa = px0[i], pb = 0.f;
            pa = fmaf(wh[i][0], hs[0], pa);
            pa = fmaf(wh[i][1], hs[1], pa);
            pa = fmaf(wh[i][2], hs[2], pa);
            pa = fmaf(wh[i][3], hs[3], pa);
            pb = fmaf(wh[i][4], hs[4], pb);
            pb = fmaf(wh[i][5], hs[5], pb);
            pb = fmaf(wh[i][6], hs[6], pb);
            pb = fmaf(wh[i][7], hs[7], pb);
            y[i] = __cosf(pa + pb);
        }

        const float A  = fmaf(s0, y[0], 1.f) * fmaf(s0, y[1], 1.f);
        const float F5 = fmaf(s5, y[2], 1.f);
        const float F6 = fmaf(s6, y[3], 1.f);
        const float F7 = fmaf(s7, y[4], 1.f);
        const float num = (A * F5) * (F6 * F7);

        const float t567 = (y[2] * y[3]) * y[4];
        float den = 8.0f * fmaf(y[0] + y[1], t567, fmaf(y[0], y[1], 1.f));
        den = fmaxf(den, 1e-30f);
        const float prob = __fdividef(num, den);

        // gather the 4 gate probabilities for this lane's qubit j (one shfl stage)
        const float pf = shfl(prob, j);
        const float pi = shfl(prob, 8 + j);
        const float pu = shfl(prob, 16 + j);
        const float po = shfl(prob, 24 + j);

        const float gg = ftanh(pu);
        c = fmaf(pf, c, pi * gg);
        h = po * ftanh(c);

        if (lane < NQ)
            out[(long)s * (BATCH * NQ) + b * NQ + lane] = h;

#pragma unroll
        for (int i = 0; i < 5; i++) { px0[i] = px1[i]; px1[i] = px2[i]; }
    }

    if (lane < NQ) {
        const long ob = (long)S_LEN * BATCH * NQ;
        out[ob + b * NQ + lane] = h;                    // h_n
        out[ob + BATCH * NQ + b * NQ + lane] = c;       // c_n
    }
}

// ---------------------------------------------------------------------------
extern "C" void kernel_launch(void* const* d_in, const int* in_sizes, int n_in,
                              void* d_out, int out_size)
{
    const float* x  = (const float*)d_in[0];
    const float* Wf = (const float*)d_in[1];
    const float* bf = (const float*)d_in[2];
    const float* Wi = (const float*)d_in[3];
    const float* bi = (const float*)d_in[4];
    const float* Wu = (const float*)d_in[5];
    const float* bu = (const float*)d_in[6];
    const float* Wo = (const float*)d_in[7];
    const float* bo = (const float*)d_in[8];
    float* out = (float*)d_out;

    px_kernel<<<2048, 160>>>(x, Wf, bf, Wi, bi, Wu, bu, Wo, bo);
    qlstm_kernel<<<BATCH, 32>>>(Wf, Wi, Wu, Wo, out);
}